// round 2
// baseline (speedup 1.0000x reference)
#include <cuda_runtime.h>

// Encoding layer: B=16, D=128, N=4096, K=32
//   xc[b,n,k] = <X[b,n,:], C[k,:]>,  SL = scale[k]*(|X|^2 - 2 xc + |C[k]|^2)
//   A = softmax_k(SL),  E[b,k,d] = sum_n A[b,n,k]*X[b,n,d] - (sum_n A[b,n,k])*C[k,d]

#define Dd    128
#define Kk    32
#define Bb    16
#define HWn   4096
#define TN    32      // n per tile
#define TILES 4       // tiles per chunk
#define CH    32      // chunks per batch (TN*TILES*CH = 4096)
#define NTH   256

#define XS 132   // Xs row stride (floats), n-major [TN][XS]
#define CS 132   // Cs row stride
#define AS 36    // As row stride

// deterministic cross-chunk partials (no atomics anywhere)
__device__ float g_scratchE[Bb*CH*Kk*Dd];   // 8 MB
__device__ float g_scratchS[Bb*CH*Kk];

using u64 = unsigned long long;

__device__ __forceinline__ u64 pack2(float lo, float hi) {
    u64 r; asm("mov.b64 %0, {%1, %2};" : "=l"(r) : "f"(lo), "f"(hi)); return r;
}
__device__ __forceinline__ float2 unpack2(u64 v) {
    float2 f; asm("mov.b64 {%0, %1}, %2;" : "=f"(f.x), "=f"(f.y) : "l"(v)); return f;
}
__device__ __forceinline__ u64 fma2(u64 a, u64 b, u64 c) {
    u64 d; asm("fma.rn.f32x2 %0, %1, %2, %3;" : "=l"(d) : "l"(a), "l"(b), "l"(c)); return d;
}
__device__ __forceinline__ u64 add2(u64 a, u64 b) {
    u64 d; asm("add.rn.f32x2 %0, %1, %2;" : "=l"(d) : "l"(a), "l"(b)); return d;
}

__global__ void __launch_bounds__(NTH, 4) enc_main(
    const float* __restrict__ x,      // (B, D, H*W)
    const float* __restrict__ cw,     // (K, D)
    const float* __restrict__ scale)  // (K,)
{
    __shared__ float Xs[TN*XS];       // n-major: Xs[n][d]
    __shared__ float Cs[Kk*CS];       // Cs[k][d]
    __shared__ float As[TN*AS];       // As[n][k]
    __shared__ float c2s[Kk];
    __shared__ float scs[Kk];

    const int tid   = threadIdx.x;
    const int b     = blockIdx.y;
    const int chunk = blockIdx.x;

    // ---- stage codewords (coalesced LDG, conflict-free STS) ----
    #pragma unroll 1
    for (int i = tid; i < Kk*Dd; i += NTH)
        Cs[(i >> 7)*CS + (i & 127)] = cw[i];
    __syncthreads();
    if (tid < Kk) {
        float s = 0.f;
        #pragma unroll 1
        for (int d = 0; d < Dd; d++) { float c = Cs[tid*CS + d]; s += c*c; }
        c2s[tid] = s;
        scs[tid] = scale[tid];
    }
    __syncthreads();

    // phase-A mapping: lane bits [2:0]=k-quad, [4:3]+warp = n
    const int ktA = tid & 7;          // k-quad index: k = 4*ktA + j
    const int nA  = tid >> 3;         // n within tile (0..31)
    const float4 c2v = *(const float4*)&c2s[ktA*4];
    const float4 scv = *(const float4*)&scs[ktA*4];

    // fill mapping
    const int nl = tid & 31;
    const int dq = tid >> 5;          // 8 d-groups of 16

    // phase-B mapping: warp -> k-quad, lane -> d-quad
    const int wB = tid >> 5;          // k base = 4*wB
    const int lB = tid & 31;          // d base = 4*lB

    u64 accB[2][4];                   // [k-pair][d] ; lo half = even k, hi = odd k
    #pragma unroll
    for (int p = 0; p < 2; p++)
        #pragma unroll
        for (int d = 0; d < 4; d++) accB[p][d] = 0ull;
    u64 sA = 0ull, sB = 0ull;         // asum pairs

    const float* xb = x + (size_t)b * Dd * HWn;

    for (int t = 0; t < TILES; t++) {
        const int n0 = chunk*(TN*TILES) + t*TN;
        __syncthreads();   // protect prior tile's Xs/As readers

        // ---- fill Xs[n][d] (coalesced scalar LDG, STS.128 at 4-phase floor) ----
        {
            const float* src = xb + (size_t)(dq*16)*HWn + n0 + nl;
            float* dst = &Xs[nl*XS + dq*16];
            #pragma unroll
            for (int j4 = 0; j4 < 4; j4++) {
                float4 v;
                v.x = src[(size_t)(4*j4+0)*HWn];
                v.y = src[(size_t)(4*j4+1)*HWn];
                v.z = src[(size_t)(4*j4+2)*HWn];
                v.w = src[(size_t)(4*j4+3)*HWn];
                *(float4*)(dst + 4*j4) = v;
            }
        }
        __syncthreads();

        // ---- phase A: xc[4] for this n over all 128 d ----
        const float* xrow = &Xs[nA*XS];
        const float* crow = &Cs[(ktA*4)*CS];

        // x2 partial over d-slice [16*ktA, 16*ktA+16), reduced over kt lanes
        u64 x2a = 0ull, x2b = 0ull;
        #pragma unroll
        for (int dd = 0; dd < 16; dd += 4) {
            double2 xd = *(const double2*)(xrow + ktA*16 + dd);
            u64 xl = __double_as_longlong(xd.x), xh = __double_as_longlong(xd.y);
            x2a = fma2(xl, xl, x2a);
            x2b = fma2(xh, xh, x2b);
        }
        float2 x2f = unpack2(add2(x2a, x2b));
        float x2 = x2f.x + x2f.y;
        x2 += __shfl_xor_sync(0xffffffffu, x2, 1);
        x2 += __shfl_xor_sync(0xffffffffu, x2, 2);
        x2 += __shfl_xor_sync(0xffffffffu, x2, 4);

        u64 xc2[4] = {0ull, 0ull, 0ull, 0ull};
        #pragma unroll 2
        for (int d0 = 0; d0 < 128; d0 += 4) {
            double2 xd = *(const double2*)(xrow + d0);
            u64 xl = __double_as_longlong(xd.x), xh = __double_as_longlong(xd.y);
            #pragma unroll
            for (int j = 0; j < 4; j++) {
                double2 cd = *(const double2*)(crow + j*CS + d0);
                xc2[j] = fma2(xl, __double_as_longlong(cd.x), xc2[j]);
                xc2[j] = fma2(xh, __double_as_longlong(cd.y), xc2[j]);
            }
        }

        // ---- softmax over K=32 (4 local k + shfl over 8 kt lanes) ----
        float sl[4];
        {
            float2 f0 = unpack2(xc2[0]), f1 = unpack2(xc2[1]);
            float2 f2 = unpack2(xc2[2]), f3 = unpack2(xc2[3]);
            sl[0] = scv.x * (x2 - 2.f*(f0.x+f0.y) + c2v.x);
            sl[1] = scv.y * (x2 - 2.f*(f1.x+f1.y) + c2v.y);
            sl[2] = scv.z * (x2 - 2.f*(f2.x+f2.y) + c2v.z);
            sl[3] = scv.w * (x2 - 2.f*(f3.x+f3.y) + c2v.w);
        }
        float m = fmaxf(fmaxf(sl[0], sl[1]), fmaxf(sl[2], sl[3]));
        m = fmaxf(m, __shfl_xor_sync(0xffffffffu, m, 1));
        m = fmaxf(m, __shfl_xor_sync(0xffffffffu, m, 2));
        m = fmaxf(m, __shfl_xor_sync(0xffffffffu, m, 4));
        float p0 = __expf(sl[0]-m), p1 = __expf(sl[1]-m);
        float p2 = __expf(sl[2]-m), p3 = __expf(sl[3]-m);
        float ssum = (p0+p1) + (p2+p3);
        ssum += __shfl_xor_sync(0xffffffffu, ssum, 1);
        ssum += __shfl_xor_sync(0xffffffffu, ssum, 2);
        ssum += __shfl_xor_sync(0xffffffffu, ssum, 4);
        float inv = 1.f / ssum;
        *(float4*)&As[nA*AS + ktA*4] = make_float4(p0*inv, p1*inv, p2*inv, p3*inv);
        __syncthreads();

        // ---- phase B: accB[k-pair][d] += A[n][k]*X[n][d] over tile n ----
        #pragma unroll 2
        for (int n = 0; n < TN; n++) {
            float4 xv = *(const float4*)&Xs[n*XS + lB*4];
            u64 a01 = __double_as_longlong(*(const double*)&As[n*AS + wB*4]);
            u64 a23 = __double_as_longlong(*(const double*)&As[n*AS + wB*4 + 2]);
            sA = add2(a01, sA);
            sB = add2(a23, sB);
            u64 xd0 = pack2(xv.x, xv.x), xd1 = pack2(xv.y, xv.y);
            u64 xd2 = pack2(xv.z, xv.z), xd3 = pack2(xv.w, xv.w);
            accB[0][0] = fma2(a01, xd0, accB[0][0]);
            accB[0][1] = fma2(a01, xd1, accB[0][1]);
            accB[0][2] = fma2(a01, xd2, accB[0][2]);
            accB[0][3] = fma2(a01, xd3, accB[0][3]);
            accB[1][0] = fma2(a23, xd0, accB[1][0]);
            accB[1][1] = fma2(a23, xd1, accB[1][1]);
            accB[1][2] = fma2(a23, xd2, accB[1][2]);
            accB[1][3] = fma2(a23, xd3, accB[1][3]);
        }
    }

    // ---- epilogue: per-chunk partials (deterministic, no atomics) ----
    {
        float2 r00 = unpack2(accB[0][0]), r01 = unpack2(accB[0][1]);
        float2 r02 = unpack2(accB[0][2]), r03 = unpack2(accB[0][3]);
        float2 r10 = unpack2(accB[1][0]), r11 = unpack2(accB[1][1]);
        float2 r12 = unpack2(accB[1][2]), r13 = unpack2(accB[1][3]);
        float* eo = g_scratchE + (((size_t)(b*CH + chunk)*Kk + 4*wB)*Dd + 4*lB);
        *(float4*)(eo + 0*Dd) = make_float4(r00.x, r01.x, r02.x, r03.x);
        *(float4*)(eo + 1*Dd) = make_float4(r00.y, r01.y, r02.y, r03.y);
        *(float4*)(eo + 2*Dd) = make_float4(r10.x, r11.x, r12.x, r13.x);
        *(float4*)(eo + 3*Dd) = make_float4(r10.y, r11.y, r12.y, r13.y);
        if (lB == 0) {
            float2 s0 = unpack2(sA), s1 = unpack2(sB);
            float* so = g_scratchS + (b*CH + chunk)*Kk + 4*wB;
            so[0] = s0.x; so[1] = s0.y; so[2] = s1.x; so[3] = s1.y;
        }
    }
}

__global__ void __launch_bounds__(128) enc_reduce(
    const float* __restrict__ cw, float* __restrict__ out)
{
    int idx = blockIdx.x*128 + threadIdx.x;   // idx = ((b*K)+k)*D + d
    int b  = idx >> 12;
    int kd = idx & 4095;
    int k  = kd >> 7;
    const float* ep = g_scratchE + (size_t)b*CH*(Kk*Dd) + kd;
    const float* sp = g_scratchS + b*CH*Kk + k;
    float e = 0.f, s = 0.f;
    #pragma unroll
    for (int c = 0; c < CH; c++) {
        e += ep[(size_t)c*(Kk*Dd)];
        s += sp[c*Kk];
    }
    out[idx] = e - s * cw[kd];
}

extern "C" void kernel_launch(void* const* d_in, const int* in_sizes, int n_in,
                              void* d_out, int out_size)
{
    const float* x  = (const float*)d_in[0];
    const float* cw = (const float*)d_in[1];
    const float* sc = (const float*)d_in[2];
    float* out = (float*)d_out;

    enc_main<<<dim3(CH, Bb), NTH>>>(x, cw, sc);
    enc_reduce<<<(Bb*Kk*Dd)/128, 128>>>(cw, out);
}

// round 3
// speedup vs baseline: 5.6776x; 5.6776x over previous
#include <cuda_runtime.h>

// Encoding layer on tensor cores (tf32 mma.sync), B=16, D=128, N=4096, K=32.
// One CTA = one (b, chunk) tile of 128 n. Pipeline:
//   fill Xs (tf32-rounded) + exact-fp32 x2 partials; fill Cs (tf32-rounded)
//   GEMM1 (xc = X C^T) -> softmax in registers -> As (tf32) -> asum
//   GEMM2 (E_part = A^T X) -> scratch; reduce kernel folds chunks, subtracts asum*C.

#define Dd   128
#define Kk   32
#define Bb   16
#define HWn  4096
#define TN   128
#define CH   32          // 4096 / TN
#define NTH  256
#define ST   132         // smem row stride (floats) for Xs/Cs/As

// float offsets into dynamic smem
#define XS_OFF   0                    // [128][ST]
#define CS_OFF   (128*ST)             // [32][ST]
#define AS_OFF   (160*ST)             // [32][ST]
#define X2P_OFF  (192*ST)             // [8][128]
#define X2S_OFF  (X2P_OFF + 1024)     // [128]
#define C2S_OFF  (X2S_OFF + 128)      // [32]
#define RED_OFF  (C2S_OFF + 32)       // [256] scratch for c2/asum partials
#define SM_FLOATS (RED_OFF + 256)
#define SM_BYTES  (SM_FLOATS * 4)

__device__ float g_scratchE[Bb*CH*Kk*Dd];   // 8 MB partial E
__device__ float g_scratchS[Bb*CH*Kk];      // partial asum

__device__ __forceinline__ unsigned f2tf(float f) {
    unsigned r; asm("cvt.rna.tf32.f32 %0, %1;" : "=r"(r) : "f"(f)); return r;
}
__device__ __forceinline__ void mma_tf32(float* d,
    unsigned a0, unsigned a1, unsigned a2, unsigned a3, unsigned b0, unsigned b1) {
    asm("mma.sync.aligned.m16n8k8.row.col.f32.tf32.tf32.f32 "
        "{%0,%1,%2,%3}, {%4,%5,%6,%7}, {%8,%9}, {%0,%1,%2,%3};"
        : "+f"(d[0]), "+f"(d[1]), "+f"(d[2]), "+f"(d[3])
        : "r"(a0), "r"(a1), "r"(a2), "r"(a3), "r"(b0), "r"(b1));
}
__device__ __forceinline__ unsigned fbits(float f) { return __float_as_uint(f); }

__global__ void __launch_bounds__(NTH) enc_main(
    const float* __restrict__ x,      // (B, D, HWn)
    const float* __restrict__ cw,     // (K, D)
    const float* __restrict__ scale)  // (K,)
{
    extern __shared__ float sm[];
    const int tid = threadIdx.x;
    const int w   = tid >> 5;         // warp 0..7
    const int l   = tid & 31;
    const int lr  = l >> 2;           // 0..7
    const int lc  = l & 3;            // 0..3
    const int b     = blockIdx.y;
    const int chunk = blockIdx.x;
    const float* xb = x + (size_t)b * Dd * HWn + chunk * TN;

    // ---- fill Cs (tf32-rounded), coalesced ----
    #pragma unroll 1
    for (int i = tid; i < Kk*Dd; i += NTH)
        sm[CS_OFF + (i >> 7)*ST + (i & 127)] = __uint_as_float(f2tf(cw[i]));

    // ---- fill Xs (tf32-rounded) + exact-fp32 x2 partials ----
    {
        const int nl = tid & 31, dq = tid >> 5;   // d in [16dq,16dq+16)
        #pragma unroll
        for (int p = 0; p < 4; p++) {
            const int n = p*32 + nl;
            const float* src = xb + (size_t)(dq*16)*HWn + n;
            float* dst = &sm[XS_OFF + n*ST + dq*16];
            float part = 0.f;
            #pragma unroll
            for (int j = 0; j < 4; j++) {
                float v0 = src[(size_t)(4*j+0)*HWn];
                float v1 = src[(size_t)(4*j+1)*HWn];
                float v2 = src[(size_t)(4*j+2)*HWn];
                float v3 = src[(size_t)(4*j+3)*HWn];
                part += v0*v0 + v1*v1 + v2*v2 + v3*v3;
                float4 o;
                o.x = __uint_as_float(f2tf(v0)); o.y = __uint_as_float(f2tf(v1));
                o.z = __uint_as_float(f2tf(v2)); o.w = __uint_as_float(f2tf(v3));
                *(float4*)(dst + 4*j) = o;
            }
            sm[X2P_OFF + dq*128 + n] = part;
        }
    }
    __syncthreads();

    // ---- c2 partials (from rounded Cs; negligible vs exact) + x2 reduce ----
    {
        int k = tid >> 3, s8 = tid & 7;
        float part = 0.f;
        #pragma unroll
        for (int j = 0; j < 16; j++) {
            float c = sm[CS_OFF + k*ST + s8*16 + j];
            part += c*c;
        }
        sm[RED_OFF + tid] = part;
    }
    if (tid < 128) {
        float s = 0.f;
        #pragma unroll
        for (int dq = 0; dq < 8; dq++) s += sm[X2P_OFF + dq*128 + tid];
        sm[X2S_OFF + tid] = s;
    }
    __syncthreads();
    if (tid < Kk) {
        float s = 0.f;
        #pragma unroll
        for (int j = 0; j < 8; j++) s += sm[RED_OFF + tid*8 + j];
        sm[C2S_OFF + tid] = s;
    }
    __syncthreads();

    // ---- per-thread softmax constants: k = 8*kt + 2*lc + j ----
    float c2v[4][2], scv[4][2];
    #pragma unroll
    for (int kt = 0; kt < 4; kt++)
        #pragma unroll
        for (int j = 0; j < 2; j++) {
            int k = 8*kt + 2*lc + j;
            c2v[kt][j] = sm[C2S_OFF + k];
            scv[kt][j] = scale[k];           // tiny, L1-cached
        }

    // ---- GEMM1: xc[n,k], warp w owns n rows [16w, 16w+16), all 32 k ----
    float D1[4][4];
    #pragma unroll
    for (int kt = 0; kt < 4; kt++)
        #pragma unroll
        for (int r = 0; r < 4; r++) D1[kt][r] = 0.f;
    const int rowA = 16*w + lr;
    #pragma unroll 4
    for (int ds = 0; ds < 16; ds++) {
        const int d0 = ds*8;
        unsigned a0 = fbits(sm[XS_OFF + rowA*ST     + d0 + lc]);
        unsigned a1 = fbits(sm[XS_OFF + (rowA+8)*ST + d0 + lc]);
        unsigned a2 = fbits(sm[XS_OFF + rowA*ST     + d0 + lc + 4]);
        unsigned a3 = fbits(sm[XS_OFF + (rowA+8)*ST + d0 + lc + 4]);
        #pragma unroll
        for (int kt = 0; kt < 4; kt++) {
            unsigned b0 = fbits(sm[CS_OFF + (8*kt+lr)*ST + d0 + lc]);
            unsigned b1 = fbits(sm[CS_OFF + (8*kt+lr)*ST + d0 + lc + 4]);
            mma_tf32(D1[kt], a0, a1, a2, a3, b0, b1);
        }
    }

    // ---- softmax over K=32: rows r0=rowA, r1=rowA+8 ----
    {
        const float x2_0 = sm[X2S_OFF + rowA];
        const float x2_1 = sm[X2S_OFF + rowA + 8];
        float sl[4][4];
        #pragma unroll
        for (int kt = 0; kt < 4; kt++) {
            sl[kt][0] = scv[kt][0]*(x2_0 - 2.f*D1[kt][0] + c2v[kt][0]);
            sl[kt][1] = scv[kt][1]*(x2_0 - 2.f*D1[kt][1] + c2v[kt][1]);
            sl[kt][2] = scv[kt][0]*(x2_1 - 2.f*D1[kt][2] + c2v[kt][0]);
            sl[kt][3] = scv[kt][1]*(x2_1 - 2.f*D1[kt][3] + c2v[kt][1]);
        }
        float m0 = -3.4e38f, m1 = -3.4e38f;
        #pragma unroll
        for (int kt = 0; kt < 4; kt++) {
            m0 = fmaxf(m0, fmaxf(sl[kt][0], sl[kt][1]));
            m1 = fmaxf(m1, fmaxf(sl[kt][2], sl[kt][3]));
        }
        m0 = fmaxf(m0, __shfl_xor_sync(~0u, m0, 1));
        m0 = fmaxf(m0, __shfl_xor_sync(~0u, m0, 2));
        m1 = fmaxf(m1, __shfl_xor_sync(~0u, m1, 1));
        m1 = fmaxf(m1, __shfl_xor_sync(~0u, m1, 2));
        float s0 = 0.f, s1 = 0.f;
        #pragma unroll
        for (int kt = 0; kt < 4; kt++) {
            sl[kt][0] = __expf(sl[kt][0] - m0); s0 += sl[kt][0];
            sl[kt][1] = __expf(sl[kt][1] - m0); s0 += sl[kt][1];
            sl[kt][2] = __expf(sl[kt][2] - m1); s1 += sl[kt][2];
            sl[kt][3] = __expf(sl[kt][3] - m1); s1 += sl[kt][3];
        }
        s0 += __shfl_xor_sync(~0u, s0, 1); s0 += __shfl_xor_sync(~0u, s0, 2);
        s1 += __shfl_xor_sync(~0u, s1, 1); s1 += __shfl_xor_sync(~0u, s1, 2);
        const float i0 = 1.f/s0, i1 = 1.f/s1;
        // store A^T (k-major) tf32-rounded: As[k][n]
        #pragma unroll
        for (int kt = 0; kt < 4; kt++)
            #pragma unroll
            for (int j = 0; j < 2; j++) {
                int k = 8*kt + 2*lc + j;
                sm[AS_OFF + k*ST + rowA]     = __uint_as_float(f2tf(sl[kt][2*0+j]*i0));
                sm[AS_OFF + k*ST + rowA + 8] = __uint_as_float(f2tf(sl[kt][2*1+j]*i1));
            }
    }
    __syncthreads();

    // ---- asum partials from the SAME rounded A ----
    {
        int k = tid >> 3, ns = tid & 7;
        float s = 0.f;
        #pragma unroll
        for (int i = 0; i < 16; i++) s += sm[AS_OFF + k*ST + ns + 8*i];
        sm[RED_OFF + tid] = s;
    }
    __syncthreads();
    if (tid < Kk) {
        float s = 0.f;
        #pragma unroll
        for (int j = 0; j < 8; j++) s += sm[RED_OFF + tid*8 + j];
        g_scratchS[(b*CH + chunk)*Kk + tid] = s;
    }

    // ---- GEMM2: E[k,d] = sum_n A[k,n] X[n,d]; warp w owns d in [16w,16w+16) ----
    float D2[2][2][4];
    #pragma unroll
    for (int mt = 0; mt < 2; mt++)
        #pragma unroll
        for (int nt = 0; nt < 2; nt++)
            #pragma unroll
            for (int r = 0; r < 4; r++) D2[mt][nt][r] = 0.f;
    const int dwarp = 16*w;
    #pragma unroll 4
    for (int ns = 0; ns < 16; ns++) {
        const int n0 = ns*8;
        unsigned bx0[2], bx1[2];
        #pragma unroll
        for (int nt = 0; nt < 2; nt++) {
            bx0[nt] = fbits(sm[XS_OFF + (n0+lc)*ST   + dwarp + 8*nt + lr]);
            bx1[nt] = fbits(sm[XS_OFF + (n0+lc+4)*ST + dwarp + 8*nt + lr]);
        }
        #pragma unroll
        for (int mt = 0; mt < 2; mt++) {
            unsigned a0 = fbits(sm[AS_OFF + (16*mt+lr)*ST   + n0 + lc]);
            unsigned a1 = fbits(sm[AS_OFF + (16*mt+lr+8)*ST + n0 + lc]);
            unsigned a2 = fbits(sm[AS_OFF + (16*mt+lr)*ST   + n0 + lc + 4]);
            unsigned a3 = fbits(sm[AS_OFF + (16*mt+lr+8)*ST + n0 + lc + 4]);
            #pragma unroll
            for (int nt = 0; nt < 2; nt++)
                mma_tf32(D2[mt][nt], a0, a1, a2, a3, bx0[nt], bx1[nt]);
        }
    }

    // ---- epilogue: partial E to scratch ----
    {
        float* eo = g_scratchE + (size_t)(b*CH + chunk)*(Kk*Dd);
        #pragma unroll
        for (int mt = 0; mt < 2; mt++)
            #pragma unroll
            for (int nt = 0; nt < 2; nt++) {
                int k0 = 16*mt + lr;
                int dc = dwarp + 8*nt + 2*lc;
                *(float2*)&eo[k0*Dd + dc]     = make_float2(D2[mt][nt][0], D2[mt][nt][1]);
                *(float2*)&eo[(k0+8)*Dd + dc] = make_float2(D2[mt][nt][2], D2[mt][nt][3]);
            }
    }
}

__global__ void __launch_bounds__(NTH) enc_reduce(
    const float* __restrict__ cw, float* __restrict__ out)
{
    int idx = blockIdx.x*NTH + threadIdx.x;   // ((b*K)+k)*D + d
    int b  = idx >> 12;
    int kd = idx & 4095;
    int k  = kd >> 7;
    const float* ep = g_scratchE + (size_t)b*CH*(Kk*Dd) + kd;
    const float* sp = g_scratchS + b*CH*Kk + k;
    float e = 0.f, s = 0.f;
    #pragma unroll
    for (int c = 0; c < CH; c++) {
        e += ep[(size_t)c*(Kk*Dd)];
        s += sp[c*Kk];
    }
    out[idx] = e - s * cw[kd];
}

extern "C" void kernel_launch(void* const* d_in, const int* in_sizes, int n_in,
                              void* d_out, int out_size)
{
    const float* x  = (const float*)d_in[0];
    const float* cw = (const float*)d_in[1];
    const float* sc = (const float*)d_in[2];
    float* out = (float*)d_out;

    cudaFuncSetAttribute(enc_main, cudaFuncAttributeMaxDynamicSharedMemorySize, SM_BYTES);
    enc_main<<<dim3(CH, Bb), NTH, SM_BYTES>>>(x, cw, sc);
    enc_reduce<<<(Bb*Kk*Dd)/NTH, NTH>>>(cw, out);
}